// round 1
// baseline (speedup 1.0000x reference)
#include <cuda_runtime.h>
#include <math_constants.h>
#include <cstdint>

// Problem constants
#define BB 4096
#define DD 1024
#define KK 32
#define MIN_BW 0.001f
#define MIN_BH 0.001f

#define NTILES (DD / 32)          // 32 feature tiles
#define ROWS_PER_BLOCK 128
#define ROWS_PER_WARP 16

// Precomputed per-feature spline data (device globals: allocation-free scratch)
__device__ float4 g_coef[DD * KK];     // {a, b, c, d} per (feature, bin)
__device__ float  g_cwl[DD * KK];      // left cumwidth per (feature, bin)
__device__ float  g_edges[DD * KK];    // 31 interior edges + INF sentinel
__device__ float  g_partial[BB * NTILES]; // per-(row, tile) log2 partial sums

static __device__ __forceinline__ float warp_sum(float v) {
    #pragma unroll
    for (int o = 16; o; o >>= 1) v += __shfl_xor_sync(0xffffffffu, v, o);
    return v;
}

// ---------------------------------------------------------------------------
// Kernel 1: per-feature coefficient precompute. One warp per feature.
// lane = bin index k (0..31).
// ---------------------------------------------------------------------------
__global__ void __launch_bounds__(256) precompute_kernel(
    const float* __restrict__ uw, const float* __restrict__ uh,
    const float* __restrict__ udl, const float* __restrict__ udr)
{
    const unsigned FULL = 0xffffffffu;
    int warpId = threadIdx.x >> 5;
    int lane   = threadIdx.x & 31;
    int f = blockIdx.x * 8 + warpId;
    if (f >= DD) return;

    float w_in = uw[f * KK + lane];
    float h_in = uh[f * KK + lane];

    // softmax(widths)
    float mx = w_in;
    #pragma unroll
    for (int o = 16; o; o >>= 1) mx = fmaxf(mx, __shfl_xor_sync(FULL, mx, o));
    float ew = __expf(w_in - mx);
    float sw = warp_sum(ew);
    float width = MIN_BW + (1.0f - MIN_BW * (float)KK) * (ew / sw);

    // softmax(heights)
    float mh = h_in;
    #pragma unroll
    for (int o = 16; o; o >>= 1) mh = fmaxf(mh, __shfl_xor_sync(FULL, mh, o));
    float eh = __expf(h_in - mh);
    float sh = warp_sum(eh);
    float height = MIN_BH + (1.0f - MIN_BH * (float)KK) * (eh / sh);

    // inclusive cumsum across lanes
    float csw = width, csh = height;
    #pragma unroll
    for (int d = 1; d < 32; d <<= 1) {
        float t = __shfl_up_sync(FULL, csw, d);
        if (lane >= d) csw += t;
        float t2 = __shfl_up_sync(FULL, csh, d);
        if (lane >= d) csh += t2;
    }

    // left edges (cumwidths/cumheights shifted, with leading 0)
    float cwL = __shfl_up_sync(FULL, csw, 1); if (lane == 0) cwL = 0.0f;
    float chL = __shfl_up_sync(FULL, csh, 1); if (lane == 0) chL = 0.0f;

    float slope  = height / width;
    float slopeN = __shfl_down_sync(FULL, slope, 1);
    float widthN = __shfl_down_sync(FULL, width, 1);

    // inner derivative at knot (lane+1), valid for lane < 31
    float min1 = fminf(fabsf(slope), fabsf(slopeN));
    float min2 = 0.5f * (widthN * slope + width * slopeN) / (width + widthN);
    float ms   = fminf(min1, min2);
    float sg   = (float)((slope  > 0.0f) - (slope  < 0.0f));
    float sgN  = (float)((slopeN > 0.0f) - (slopeN < 0.0f));
    float dInnerR = ms * (sg + sgN);

    float s0  = __shfl_sync(FULL, slope, 0);
    float s31 = __shfl_sync(FULL, slope, 31);
    float dl = (1.0f / (1.0f + __expf(-udl[f]))) * 3.0f * s0;
    float dr = (1.0f / (1.0f + __expf(-udr[f]))) * 3.0f * s31;

    float derivR = (lane == 31) ? dr : dInnerR;
    float derivL = __shfl_up_sync(FULL, derivR, 1);
    if (lane == 0) derivL = dl;

    float a = (derivL + derivR - 2.0f * slope) / (width * width);
    float b = (3.0f * slope - 2.0f * derivL - derivR) / width;
    float c = derivL;
    float dcoef = chL;

    int idx = f * KK + lane;
    g_coef[idx]  = make_float4(a, b, c, dcoef);
    g_cwl[idx]   = cwL;
    g_edges[idx] = (lane == 31) ? CUDART_INF_F : csw; // edges[i]=cumwidth[i], i<31
}

// ---------------------------------------------------------------------------
// Kernel 2: main evaluation.
// grid = (NTILES, BB/ROWS_PER_BLOCK). Block: 256 thr = 8 warps.
// Each warp: lane <-> feature (32 features of tile), 16 batch rows.
// ---------------------------------------------------------------------------
__global__ void __launch_bounds__(256) spline_kernel(
    const float* __restrict__ inputs, float* __restrict__ outputs)
{
    __shared__ float  sh_edges[32 * 33];
    __shared__ float  sh_cwl  [32 * 33];
    __shared__ float4 sh_coef [32 * 33];

    const unsigned FULL = 0xffffffffu;
    int tid    = threadIdx.x;
    int warpId = tid >> 5;
    int lane   = tid & 31;
    int tileBase = blockIdx.x * 32;

    // stage coefficient tile into shared (pitch 33 to avoid bank conflicts)
    for (int i = tid; i < 32 * 32; i += 256) {
        int f = i >> 5, j = i & 31;
        int gidx = (tileBase + f) * KK + j;
        int sidx = f * 33 + j;
        sh_edges[sidx] = g_edges[gidx];
        sh_cwl[sidx]   = g_cwl[gidx];
        sh_coef[sidx]  = g_coef[gidx];
    }
    __syncthreads();

    int rowBase = blockIdx.y * ROWS_PER_BLOCK + warpId * ROWS_PER_WARP;
    int base = lane * 33;

    float xs[ROWS_PER_WARP];
    #pragma unroll
    for (int r = 0; r < ROWS_PER_WARP; r++)
        xs[r] = inputs[(size_t)(rowBase + r) * DD + tileBase + lane];

    #pragma unroll
    for (int r = 0; r < ROWS_PER_WARP; r++) {
        float x = xs[r];

        // branchless binary count over 32 sorted edges (last = INF)
        int cnt = 0;
        #pragma unroll
        for (int s = 16; s >= 1; s >>= 1)
            if (sh_edges[base + cnt + s - 1] <= x) cnt += s;

        float4 cf = sh_coef[base + cnt];
        float  cl = sh_cwl[base + cnt];

        float s = x - cl;
        float out = fmaf(fmaf(fmaf(cf.x, s, cf.y), s, cf.z), s, cf.w);
        out = __saturatef(out);
        outputs[(size_t)(rowBase + r) * DD + tileBase + lane] = out;

        float deriv = fmaf(fmaf(3.0f * cf.x, s, 2.0f * cf.y), s, cf.z);
        float ad = fabsf(deriv);

        // exponent/mantissa split: one log2 per 32 elements
        int bits = __float_as_int(ad);
        int ee = bits >> 23;
        float fe, m;
        if (ee == 0 || ee == 255) {       // zero/denormal/inf/nan fallback
            fe = __log2f(ad);
            m = 1.0f;
        } else {
            fe = (float)(ee - 127);
            m = __int_as_float((bits & 0x007FFFFF) | 0x3F800000);
        }
        #pragma unroll
        for (int o = 16; o; o >>= 1) {
            fe += __shfl_xor_sync(FULL, fe, o);
            m  *= __shfl_xor_sync(FULL, m, o);
        }
        if (lane == 0)
            g_partial[(size_t)(rowBase + r) * NTILES + blockIdx.x] = fe + __log2f(m);
    }
}

// ---------------------------------------------------------------------------
// Kernel 3: reduce NTILES partials per row -> natural-log sum
// ---------------------------------------------------------------------------
__global__ void __launch_bounds__(256) reduce_kernel(float* __restrict__ sums)
{
    int warpId = threadIdx.x >> 5;
    int lane   = threadIdx.x & 31;
    int row = blockIdx.x * 8 + warpId;
    if (row >= BB) return;
    float v = g_partial[row * NTILES + lane];
    v = warp_sum(v);
    if (lane == 0) sums[row] = v * 0.69314718055994531f; // ln(2)
}

extern "C" void kernel_launch(void* const* d_in, const int* in_sizes, int n_in,
                              void* d_out, int out_size)
{
    const float* inputs = (const float*)d_in[0];
    const float* uw     = (const float*)d_in[1];
    const float* uh     = (const float*)d_in[2];
    const float* udl    = (const float*)d_in[3];
    const float* udr    = (const float*)d_in[4];
    float* out = (float*)d_out;

    // output layout: [B*D outputs][B logabsdet sums]
    precompute_kernel<<<DD / 8, 256>>>(uw, uh, udl, udr);
    dim3 grid(NTILES, BB / ROWS_PER_BLOCK);
    spline_kernel<<<grid, 256>>>(inputs, out);
    reduce_kernel<<<BB / 8, 256>>>(out + (size_t)BB * DD);
}